// round 16
// baseline (speedup 1.0000x reference)
#include <cuda_runtime.h>
#include <cstdint>

#define NCOLS 8192
#define NROWS 8192
#define THREADS 256
#define NWARP (THREADS / 32)

__global__ __launch_bounds__(THREADS) void a4_quant_kernel(
    const float* __restrict__ x, const int* __restrict__ perm,
    float* __restrict__ out)
{
    extern __shared__ float srow[];  // one row: NCOLS floats = 32 KB
    const size_t row = (size_t)blockIdx.x;

    // ---- Permutation dtype sniff (warp-uniform, L1/L2-hot) ----
    // As int32 words: an int64 perm (values < 8192) has all-zero odd words;
    // an int32 perm has at most one zero among any 64 odd words.
    const int lane = threadIdx.x & 31;
    const int hiw = perm[2 * lane + 1] | perm[2 * lane + 65];
    const bool is64 = (__ballot_sync(0xffffffffu, hiw != 0) == 0u);

    // ---- Stage one row into SMEM via cp.async ----
    {
        const char* src = (const char*)(x + row * NCOLS);
        unsigned s = (unsigned)__cvta_generic_to_shared(srow);
        #pragma unroll
        for (int i = threadIdx.x; i < NCOLS / 4; i += THREADS) {
            asm volatile("cp.async.cg.shared.global [%0], [%1], 16;\n"
                         :: "r"(s + i * 16), "l"(src + (size_t)i * 16));
        }
        asm volatile("cp.async.commit_group;\n"
                     "cp.async.wait_group 0;\n" ::: "memory");
    }
    __syncthreads();

    const int warp = threadIdx.x >> 5;
    const int kblk = lane >> 3;   // which of the warp's 4 blocks this lane serves
    const int g    = lane & 7;    // lane within the 8-lane block group

    float* orow = out + row * NCOLS;

    // Warp iteration covers a 128-column span = 4 quant blocks of 32.
    // Lanes 8k..8k+7 own block k; lane handles 4 consecutive columns.
    for (int s = warp; s < NCOLS / 128; s += NWARP) {
        const int col0 = (s * 4 + kblk) * 32 + g * 4;

        // Index load straight from the input buffer (L1/L2-hot)
        int4 c4;
        if (is64) {
            const int4 a = *(const int4*)(perm + 2 * col0);
            const int4 b = *(const int4*)(perm + 2 * col0 + 4);
            c4 = make_int4(a.x, a.z, b.x, b.z);   // low words of 4 int64s
        } else {
            c4 = *(const int4*)(perm + col0);
        }

        // Random-bank LDS.32 gather, 4-way ILP
        const unsigned b0 = __float_as_uint(srow[c4.x]);
        const unsigned b1 = __float_as_uint(srow[c4.y]);
        const unsigned b2 = __float_as_uint(srow[c4.z]);
        const unsigned b3 = __float_as_uint(srow[c4.w]);

        const unsigned u0 = b0 & 0x7fffffffu;
        const unsigned u1 = b1 & 0x7fffffffu;
        const unsigned u2 = b2 & 0x7fffffffu;
        const unsigned u3 = b3 & 0x7fffffffu;

        // Block amax (uint max == float max for abs bits): local then
        // 8-lane butterfly reduce.
        unsigned um = max(max(u0, u1), max(u2, u3));
        um = max(um, __shfl_xor_sync(0xffffffffu, um, 1));
        um = max(um, __shfl_xor_sync(0xffffffffu, um, 2));
        um = max(um, __shfl_xor_sync(0xffffffffu, um, 4));

        // Clamp amax exponent so threshold arithmetic never underflows
        // (only reachable for amax < 2^-122; abs err < 2^-122).
        const unsigned m2   = max(um, 0x02800000u);
        const unsigned mexp = m2 & 0x7f800000u;      // 2^E bits
        const unsigned six  = mexp | 0x00400000u;    // 6   * 2^(E-2)
        const unsigned one  = mexp - 0x01000000u;    // 1   * 2^(E-2)
        const unsigned half = mexp - 0x01800000u;    // 0.5 * 2^(E-2)
        const unsigned t075 = half | 0x00400000u;    // 0.75* 2^(E-2)
        const unsigned t025 = mexp - 0x02000000u;    // 0.25* 2^(E-2)

        // FP4 E2M1 quantization in output scale, ties round UP
        // (matches searchsorted(FP4_MID, mag, side="right")).
        uint4 qv;
        {
            const unsigned r = (min(u0, six) + 0x00200000u) & 0xffc00000u;
            const unsigned q = (u0 >= one) ? r
                             : (u0 >= t075) ? one
                             : (u0 >= t025) ? half : 0u;
            qv.x = q | (b0 & 0x80000000u);
        }
        {
            const unsigned r = (min(u1, six) + 0x00200000u) & 0xffc00000u;
            const unsigned q = (u1 >= one) ? r
                             : (u1 >= t075) ? one
                             : (u1 >= t025) ? half : 0u;
            qv.y = q | (b1 & 0x80000000u);
        }
        {
            const unsigned r = (min(u2, six) + 0x00200000u) & 0xffc00000u;
            const unsigned q = (u2 >= one) ? r
                             : (u2 >= t075) ? one
                             : (u2 >= t025) ? half : 0u;
            qv.z = q | (b2 & 0x80000000u);
        }
        {
            const unsigned r = (min(u3, six) + 0x00200000u) & 0xffc00000u;
            const unsigned q = (u3 >= one) ? r
                             : (u3 >= t075) ? one
                             : (u3 >= t025) ? half : 0u;
            qv.w = q | (b3 & 0x80000000u);
        }

        // STG.128 of 4 consecutive output columns
        *(uint4*)(orow + col0) = qv;
    }
}

extern "C" void kernel_launch(void* const* d_in, const int* in_sizes, int n_in,
                              void* d_out, int out_size)
{
    // Identify inputs by element count (x: 8192*8192, permutation: 8192)
    const float* x     = nullptr;
    const void*  permb = nullptr;
    if (n_in >= 2 && in_sizes[0] == NCOLS) {
        permb = d_in[0];
        x     = (const float*)d_in[1];
    } else {
        x     = (const float*)d_in[0];
        permb = d_in[1];
    }
    float* out = (float*)d_out;

    const int smem_bytes = NCOLS * (int)sizeof(float);  // 32 KB
    cudaFuncSetAttribute(a4_quant_kernel,
                         cudaFuncAttributeMaxDynamicSharedMemorySize, smem_bytes);
    a4_quant_kernel<<<NROWS, THREADS, smem_bytes>>>(x, (const int*)permb, out);
}

// round 17
// speedup vs baseline: 1.0686x; 1.0686x over previous
#include <cuda_runtime.h>
#include <cstdint>

#define NCOLS 8192
#define NROWS 8192
#define THREADS 512
#define NWARP (THREADS / 32)
#define ROW_BYTES (NCOLS * 4)

__global__ __launch_bounds__(THREADS) void a4_quant_kernel(
    const float* __restrict__ x, const int* __restrict__ perm,
    float* __restrict__ out)
{
    extern __shared__ float srow[];            // one row: 32 KB
    __shared__ alignas(8) unsigned long long mbar;

    const size_t row = (size_t)blockIdx.x;
    const unsigned bar  = (unsigned)__cvta_generic_to_shared(&mbar);
    const unsigned sdst = (unsigned)__cvta_generic_to_shared(srow);

    // ---- Init mbarrier, then kick one bulk copy of the whole row ----
    if (threadIdx.x == 0) {
        asm volatile("mbarrier.init.shared.b64 [%0], 1;" :: "r"(bar) : "memory");
    }
    __syncthreads();
    if (threadIdx.x == 0) {
        asm volatile(
            "mbarrier.arrive.expect_tx.shared.b64 _, [%0], %1;"
            :: "r"(bar), "r"(ROW_BYTES) : "memory");
        asm volatile(
            "cp.async.bulk.shared::cta.global.mbarrier::complete_tx::bytes "
            "[%0], [%1], %2, [%3];"
            :: "r"(sdst), "l"(x + row * NCOLS), "r"(ROW_BYTES), "r"(bar)
            : "memory");
    }

    // ---- Permutation dtype sniff while the bulk copy flies ----
    // As int32 words: an int64 perm (values < 8192) has all-zero odd words;
    // an int32 perm has at most one zero among any 64 odd words.
    const int lane = threadIdx.x & 31;
    const int hiw = perm[2 * lane + 1] | perm[2 * lane + 65];
    const bool is64 = (__ballot_sync(0xffffffffu, hiw != 0) == 0u);

    // ---- Wait for the row (acquire) ----
    {
        unsigned done;
        asm volatile(
            "{\n\t.reg .pred p;\n\t"
            "mbarrier.try_wait.parity.acquire.cta.shared::cta.b64 p, [%1], %2;\n\t"
            "selp.b32 %0, 1, 0, p;\n\t}"
            : "=r"(done) : "r"(bar), "r"(0) : "memory");
        if (!done) {
            asm volatile(
                "{\n\t.reg .pred P1;\n\t"
                "WL_%=:\n\t"
                "mbarrier.try_wait.parity.acquire.cta.shared::cta.b64 P1, [%0], %1, 0x989680;\n\t"
                "@P1 bra.uni WD_%=;\n\t"
                "bra.uni WL_%=;\n\t"
                "WD_%=:\n\t}"
                :: "r"(bar), "r"(0) : "memory");
        }
    }

    const int warp = threadIdx.x >> 5;
    const int kblk = lane >> 3;   // which of the warp's 4 blocks this lane serves
    const int g    = lane & 7;    // lane within the 8-lane block group

    float* orow = out + row * NCOLS;

    // Warp iteration covers a 128-column span = 4 quant blocks of 32.
    // Lanes 8k..8k+7 own block k; lane handles 4 consecutive columns.
    for (int s = warp; s < NCOLS / 128; s += NWARP) {
        const int col0 = (s * 4 + kblk) * 32 + g * 4;

        // Index load straight from the input buffer (L1/L2-hot)
        int4 c4;
        if (is64) {
            const int4 a = *(const int4*)(perm + 2 * col0);
            const int4 b = *(const int4*)(perm + 2 * col0 + 4);
            c4 = make_int4(a.x, a.z, b.x, b.z);   // low words of 4 int64s
        } else {
            c4 = *(const int4*)(perm + col0);
        }

        // Random-bank LDS.32 gather, 4-way ILP
        const unsigned b0 = __float_as_uint(srow[c4.x]);
        const unsigned b1 = __float_as_uint(srow[c4.y]);
        const unsigned b2 = __float_as_uint(srow[c4.z]);
        const unsigned b3 = __float_as_uint(srow[c4.w]);

        const unsigned u0 = b0 & 0x7fffffffu;
        const unsigned u1 = b1 & 0x7fffffffu;
        const unsigned u2 = b2 & 0x7fffffffu;
        const unsigned u3 = b3 & 0x7fffffffu;

        // Block amax (uint max == float max for abs bits): local then
        // 8-lane butterfly reduce.
        unsigned um = max(max(u0, u1), max(u2, u3));
        um = max(um, __shfl_xor_sync(0xffffffffu, um, 1));
        um = max(um, __shfl_xor_sync(0xffffffffu, um, 2));
        um = max(um, __shfl_xor_sync(0xffffffffu, um, 4));

        // Clamp amax exponent so threshold arithmetic never underflows
        // (only reachable for amax < 2^-122; abs err < 2^-122).
        const unsigned m2   = max(um, 0x02800000u);
        const unsigned mexp = m2 & 0x7f800000u;      // 2^E bits
        const unsigned six  = mexp | 0x00400000u;    // 6   * 2^(E-2)
        const unsigned one  = mexp - 0x01000000u;    // 1   * 2^(E-2)
        const unsigned half = mexp - 0x01800000u;    // 0.5 * 2^(E-2)
        const unsigned t075 = half | 0x00400000u;    // 0.75* 2^(E-2)
        const unsigned t025 = mexp - 0x02000000u;    // 0.25* 2^(E-2)

        // FP4 E2M1 quantization in output scale, ties round UP
        // (matches searchsorted(FP4_MID, mag, side="right")).
        uint4 qv;
        {
            const unsigned r = (min(u0, six) + 0x00200000u) & 0xffc00000u;
            const unsigned q = (u0 >= one) ? r
                             : (u0 >= t075) ? one
                             : (u0 >= t025) ? half : 0u;
            qv.x = q | (b0 & 0x80000000u);
        }
        {
            const unsigned r = (min(u1, six) + 0x00200000u) & 0xffc00000u;
            const unsigned q = (u1 >= one) ? r
                             : (u1 >= t075) ? one
                             : (u1 >= t025) ? half : 0u;
            qv.y = q | (b1 & 0x80000000u);
        }
        {
            const unsigned r = (min(u2, six) + 0x00200000u) & 0xffc00000u;
            const unsigned q = (u2 >= one) ? r
                             : (u2 >= t075) ? one
                             : (u2 >= t025) ? half : 0u;
            qv.z = q | (b2 & 0x80000000u);
        }
        {
            const unsigned r = (min(u3, six) + 0x00200000u) & 0xffc00000u;
            const unsigned q = (u3 >= one) ? r
                             : (u3 >= t075) ? one
                             : (u3 >= t025) ? half : 0u;
            qv.w = q | (b3 & 0x80000000u);
        }

        // STG.128 of 4 consecutive output columns
        *(uint4*)(orow + col0) = qv;
    }
}

extern "C" void kernel_launch(void* const* d_in, const int* in_sizes, int n_in,
                              void* d_out, int out_size)
{
    // Identify inputs by element count (x: 8192*8192, permutation: 8192)
    const float* x     = nullptr;
    const void*  permb = nullptr;
    if (n_in >= 2 && in_sizes[0] == NCOLS) {
        permb = d_in[0];
        x     = (const float*)d_in[1];
    } else {
        x     = (const float*)d_in[0];
        permb = d_in[1];
    }
    float* out = (float*)d_out;

    const int smem_bytes = ROW_BYTES;   // 32 KB dynamic
    cudaFuncSetAttribute(a4_quant_kernel,
                         cudaFuncAttributeMaxDynamicSharedMemorySize, smem_bytes);
    a4_quant_kernel<<<NROWS, THREADS, smem_bytes>>>(x, (const int*)permb, out);
}